// round 1
// baseline (speedup 1.0000x reference)
#include <cuda_runtime.h>
#include <cstdint>

#define B_   16
#define CIN  256
#define CR   32
#define HW   4096          // 64*64
#define COUT 560           // 32 + 528

// 8 MB scratch for relu(BN(1x1conv(x))) in NCHW
__device__ float g_z[B_ * CR * HW];

__device__ __forceinline__ unsigned long long pack2(float lo, float hi) {
    unsigned long long r;
    asm("mov.b64 %0, {%1, %2};" : "=l"(r) : "r"(__float_as_uint(lo)), "r"(__float_as_uint(hi)));
    return r;
}
__device__ __forceinline__ unsigned long long fma2(unsigned long long a,
                                                   unsigned long long b,
                                                   unsigned long long c) {
    unsigned long long d;
    asm("fma.rn.f32x2 %0, %1, %2, %3;" : "=l"(d) : "l"(a), "l"(b), "l"(c));
    return d;
}
__device__ __forceinline__ void unpack2(unsigned long long v, float& lo, float& hi) {
    unsigned int l, h;
    asm("mov.b64 {%0, %1}, %2;" : "=r"(l), "=r"(h) : "l"(v));
    lo = __uint_as_float(l);
    hi = __uint_as_float(h);
}

// ---------------------------------------------------------------------------
// Kernel 1: 1x1 reduce conv (folded BN) + ReLU  ->  g_z
// 128 threads, 2 pixels/thread, f32x2 over output-channel pairs.
// ---------------------------------------------------------------------------
__global__ __launch_bounds__(128, 2) void k_reduce(
    const float* __restrict__ x, const float* __restrict__ w,
    const float* __restrict__ gamma, const float* __restrict__ beta,
    const float* __restrict__ mean, const float* __restrict__ var)
{
    __shared__ __align__(16) float wsm[CIN * CR];  // [c][o], BN-folded
    __shared__ float inv_s[CR];
    __shared__ float bias_s[CR];

    const int tid = threadIdx.x;
    if (tid < CR) {
        float inv = gamma[tid] / sqrtf(var[tid] + 1e-5f);
        inv_s[tid]  = inv;
        bias_s[tid] = beta[tid] - mean[tid] * inv;
    }
    __syncthreads();
    for (int i = tid; i < CIN * CR; i += 128) {
        int c = i >> 5, o = i & 31;
        wsm[i] = w[o * CIN + c] * inv_s[o];
    }
    __syncthreads();

    const int base = blockIdx.x * 256;
    const int pA = base + tid;
    const int pB = pA + 128;
    const int b  = pA >> 12;                 // 256 pixels never cross an image
    const int sA = pA & 4095;
    const int sB = pB & 4095;
    const float* xA = x + (size_t)b * CIN * HW + sA;
    const float* xB = x + (size_t)b * CIN * HW + sB;

    unsigned long long accA[16], accB[16];
#pragma unroll
    for (int m = 0; m < 16; m++) { accA[m] = 0ull; accB[m] = 0ull; }

#pragma unroll 4
    for (int c = 0; c < CIN; c++) {
        float a  = __ldg(xA + c * HW);
        float bb = __ldg(xB + c * HW);
        unsigned long long a2 = pack2(a, a);
        unsigned long long b2 = pack2(bb, bb);
        const ulonglong2* wr = reinterpret_cast<const ulonglong2*>(wsm + c * CR);
#pragma unroll
        for (int q = 0; q < 8; q++) {
            ulonglong2 w2 = wr[q];               // channels 4q..4q+3 (2 pairs)
            accA[2 * q]     = fma2(a2, w2.x, accA[2 * q]);
            accA[2 * q + 1] = fma2(a2, w2.y, accA[2 * q + 1]);
            accB[2 * q]     = fma2(b2, w2.x, accB[2 * q]);
            accB[2 * q + 1] = fma2(b2, w2.y, accB[2 * q + 1]);
        }
    }

    float* zA = g_z + b * CR * HW + sA;
    float* zB = g_z + b * CR * HW + sB;
#pragma unroll
    for (int m = 0; m < 16; m++) {
        float v0, v1;
        unpack2(accA[m], v0, v1);
        zA[(2 * m) * HW]     = fmaxf(v0 + bias_s[2 * m], 0.f);
        zA[(2 * m + 1) * HW] = fmaxf(v1 + bias_s[2 * m + 1], 0.f);
        unpack2(accB[m], v0, v1);
        zB[(2 * m) * HW]     = fmaxf(v0 + bias_s[2 * m], 0.f);
        zB[(2 * m + 1) * HW] = fmaxf(v1 + bias_s[2 * m + 1], 0.f);
    }
}

// ---------------------------------------------------------------------------
// Kernel 2: depthwise 3x3 (SAME) + scale, L2-normalize both, triu pairs,
// concat write.  16x16 pixel tile / block, 256 threads (1 px/thread).
// ---------------------------------------------------------------------------
__global__ __launch_bounds__(256, 2) void k_head(
    const float* __restrict__ dw, const float* __restrict__ scale,
    float* __restrict__ out)
{
    __shared__ float zt_s[CR * 18 * 18];   // [c][y][x], halo'd tile (41.5 KB)
    __shared__ float dws[CR * 9];
    __shared__ float sc_s[CR];

    const int tid = threadIdx.x;
    const int b   = blockIdx.z;
    const int ty0 = blockIdx.y * 16;
    const int tx0 = blockIdx.x * 16;

    for (int i = tid; i < CR * 9; i += 256) dws[i] = dw[i];
    if (tid < CR) sc_s[tid] = scale[tid];

    const float* zb = g_z + b * CR * HW;
    for (int i = tid; i < CR * 324; i += 256) {
        int c  = i / 324;
        int r  = i - c * 324;
        int y  = r / 18;
        int xx = r - y * 18;
        int gy = ty0 - 1 + y;
        int gx = tx0 - 1 + xx;
        float v = 0.f;
        if ((unsigned)gy < 64u && (unsigned)gx < 64u)
            v = zb[(c << 12) + (gy << 6) + gx];
        zt_s[i] = v;
    }
    __syncthreads();

    const int ty = tid >> 4, tx = tid & 15;

    float zv[CR];   // center values -> later z_norm
    float zc[CR];   // conv results  -> later z_tw_norm
    float ssz = 0.f, sst = 0.f;

#pragma unroll
    for (int c = 0; c < CR; c++) {
        const float* p = zt_s + c * 324 + ty * 18 + tx;  // top-left of 3x3
        float t00 = p[0],  t01 = p[1],  t02 = p[2];
        float t10 = p[18], t11 = p[19], t12 = p[20];
        float t20 = p[36], t21 = p[37], t22 = p[38];
        const float* k9 = dws + c * 9;
        float acc = t00 * k9[0];
        acc = fmaf(t01, k9[1], acc);
        acc = fmaf(t02, k9[2], acc);
        acc = fmaf(t10, k9[3], acc);
        acc = fmaf(t11, k9[4], acc);
        acc = fmaf(t12, k9[5], acc);
        acc = fmaf(t20, k9[6], acc);
        acc = fmaf(t21, k9[7], acc);
        acc = fmaf(t22, k9[8], acc);
        acc *= sc_s[c];
        zv[c] = t11;
        zc[c] = acc;
        ssz = fmaf(t11, t11, ssz);
        sst = fmaf(acc, acc, sst);
    }

    const float invz = 1.f / fmaxf(sqrtf(ssz), 1e-6f);
    const float invt = 1.f / fmaxf(sqrtf(sst), 1e-6f);

    const int s = ((ty0 + ty) << 6) + (tx0 + tx);
    float* op = out + (size_t)b * COUT * HW + s;

#pragma unroll
    for (int c = 0; c < CR; c++) {
        zv[c] *= invz;                  // z_norm
        zc[c] *= invt;                  // z_tw_norm
        op[c * HW] = zv[c];
    }

    int k = CR;
#pragma unroll
    for (int i = 0; i < CR; i++) {
#pragma unroll
        for (int j = i; j < CR; j++) {
            op[(size_t)k * HW] = zv[i] * zc[j];
            k++;
        }
    }
}

extern "C" void kernel_launch(void* const* d_in, const int* in_sizes, int n_in,
                              void* d_out, int out_size)
{
    const float* x     = (const float*)d_in[0];
    const float* w     = (const float*)d_in[1];
    const float* gamma = (const float*)d_in[2];
    const float* beta  = (const float*)d_in[3];
    const float* mean  = (const float*)d_in[4];
    const float* var   = (const float*)d_in[5];
    const float* dw    = (const float*)d_in[6];
    const float* scale = (const float*)d_in[7];

    k_reduce<<<256, 128>>>(x, w, gamma, beta, mean, var);
    k_head<<<dim3(4, 4, 16), 256>>>(dw, scale, (float*)d_out);
}

// round 2
// speedup vs baseline: 1.1669x; 1.1669x over previous
#include <cuda_runtime.h>
#include <cstdint>

#define B_   16
#define CIN  256
#define CR   32
#define HW   4096          // 64*64
#define COUT 560           // 32 + 528

// 16 MB scratch: two K-half partial sums of the 1x1 conv (BN-scale folded,
// bias/ReLU deferred to k_head)
__device__ float g_zp[2][B_ * CR * HW];

__device__ __forceinline__ unsigned long long pack2(float lo, float hi) {
    unsigned long long r;
    asm("mov.b64 %0, {%1, %2};" : "=l"(r) : "r"(__float_as_uint(lo)), "r"(__float_as_uint(hi)));
    return r;
}
__device__ __forceinline__ unsigned long long fma2(unsigned long long a,
                                                   unsigned long long b,
                                                   unsigned long long c) {
    unsigned long long d;
    asm("fma.rn.f32x2 %0, %1, %2, %3;" : "=l"(d) : "l"(a), "l"(b), "l"(c));
    return d;
}
__device__ __forceinline__ void unpack2(unsigned long long v, float& lo, float& hi) {
    unsigned int l, h;
    asm("mov.b64 {%0, %1}, %2;" : "=r"(l), "=r"(h) : "l"(v));
    lo = __uint_as_float(l);
    hi = __uint_as_float(h);
}

// ---------------------------------------------------------------------------
// Kernel 1: 1x1 reduce conv, K-split in 2.  grid (256 pixel-blocks, 2 k-halves),
// 256 threads, 1 pixel/thread, f32x2 over output-channel pairs.
// ---------------------------------------------------------------------------
__global__ __launch_bounds__(256, 3) void k_reduce(
    const float* __restrict__ x, const float* __restrict__ w,
    const float* __restrict__ gamma, const float* __restrict__ var)
{
    __shared__ __align__(16) float wsm[128 * CR];  // [c_local][o], BN inv folded
    __shared__ float inv_s[CR];

    const int tid = threadIdx.x;
    const int kh  = blockIdx.y;          // 0 or 1: input channels kh*128..+128

    if (tid < CR)
        inv_s[tid] = gamma[tid] * rsqrtf(var[tid] + 1e-5f);
    __syncthreads();
    for (int i = tid; i < 128 * CR; i += 256) {
        int c = i >> 5, o = i & 31;                 // c local
        wsm[i] = w[o * CIN + kh * 128 + c] * inv_s[o];
    }
    __syncthreads();

    const int pix = blockIdx.x * 256 + tid;
    const int b   = pix >> 12;
    const int s   = pix & 4095;
    const float* xp = x + ((size_t)(b * CIN + kh * 128) << 12) + s;

    unsigned long long acc[16];
#pragma unroll
    for (int m = 0; m < 16; m++) acc[m] = 0ull;

#pragma unroll 4
    for (int c = 0; c < 128; c++) {
        float a = __ldg(xp + (c << 12));
        unsigned long long a2 = pack2(a, a);
        const ulonglong2* wr = reinterpret_cast<const ulonglong2*>(wsm + c * CR);
#pragma unroll
        for (int q = 0; q < 8; q++) {
            ulonglong2 w2 = wr[q];            // out channels 4q..4q+3
            acc[2 * q]     = fma2(a2, w2.x, acc[2 * q]);
            acc[2 * q + 1] = fma2(a2, w2.y, acc[2 * q + 1]);
        }
    }

    float* zp = g_zp[kh] + ((size_t)(b * CR) << 12) + s;
#pragma unroll
    for (int m = 0; m < 16; m++) {
        float v0, v1;
        unpack2(acc[m], v0, v1);
        zp[(2 * m) << 12]       = v0;
        zp[(2 * m + 1) << 12]   = v1;
    }
}

// ---------------------------------------------------------------------------
// Kernel 2: combine K-halves + bias + ReLU, depthwise 3x3 + scale, dual
// L2-normalize, triu pair products, concat write.
// 32x4 pixel tile, 256 threads = 2 threads/pixel (output-channel split).
// ---------------------------------------------------------------------------
#define TW 32
#define TH 4
#define ROWW 34                       // TW + 2 halo
#define CH_STRIDE (6 * ROWW)          // 204 floats per channel tile

// triu pair index for (i,j), i<=j:  k = 32i - i(i-1)/2 + (j-i)
template<int KLO, int KHI>
__device__ __forceinline__ void emit_pairs(const float* __restrict__ ztC,
                                           const float* __restrict__ zcp,
                                           float sIJ, float* __restrict__ op)
{
#pragma unroll
    for (int i = 0; i < CR; i++) {
#pragma unroll
        for (int j = i; j < CR; j++) {
            const int k = CR * i - (i * (i - 1)) / 2 + (j - i);
            if (k >= KLO && k < KHI) {
                float zi = ztC[i * CH_STRIDE];     // raw relu'd center, ch i
                float zj = zcp[j * 128];           // raw conv*scale, ch j
                op[(size_t)(CR + k) * HW] = zi * (zj * sIJ);
            }
        }
    }
}

__global__ __launch_bounds__(256, 3) void k_head(
    const float* __restrict__ gamma, const float* __restrict__ beta,
    const float* __restrict__ mean,  const float* __restrict__ var,
    const float* __restrict__ dw,    const float* __restrict__ scale,
    float* __restrict__ out)
{
    __shared__ float zt[CR * CH_STRIDE];     // relu'd z tile with halo (25.5KB)
    __shared__ float zc_s[CR * 128];         // raw conv*scale per pixel (16KB)
    __shared__ float ssz_s[2][128];
    __shared__ float sst_s[2][128];
    __shared__ float dws[CR * 9];
    __shared__ float sc_s[CR];
    __shared__ float bias_s[CR];

    const int tid  = threadIdx.x;
    const int b    = blockIdx.z;
    const int ty0  = blockIdx.y * TH;
    const int tx0  = blockIdx.x * TW;
    const int half = tid >> 7;               // 0 or 1
    const int p    = tid & 127;              // pixel within tile
    const int ty   = p >> 5;
    const int tx   = p & 31;

    if (tid < CR) {
        float inv = gamma[tid] * rsqrtf(var[tid] + 1e-5f);
        bias_s[tid] = beta[tid] - mean[tid] * inv;
        sc_s[tid]   = scale[tid];
    }
    for (int i = tid; i < CR * 9; i += 256) dws[i] = dw[i];
    __syncthreads();   // bias_s ready before tile load uses it

    // ---- load halo'd tile: z = relu(part0 + part1 + bias) ----
    const float* z0 = g_zp[0] + ((size_t)(b * CR) << 12);
    const float* z1 = g_zp[1] + ((size_t)(b * CR) << 12);
    for (int i = tid; i < CR * CH_STRIDE; i += 256) {
        int c  = i / CH_STRIDE;
        int r  = i - c * CH_STRIDE;
        int y  = r / ROWW;
        int xx = r - y * ROWW;
        int gy = ty0 - 1 + y;
        int gx = tx0 - 1 + xx;
        float v = 0.f;
        if ((unsigned)gy < 64u && (unsigned)gx < 64u) {
            int off = (c << 12) + (gy << 6) + gx;
            v = fmaxf(z0[off] + z1[off] + bias_s[c], 0.f);
        }
        zt[i] = v;
    }
    __syncthreads();

    // ---- conv: each thread does 16 channels for its pixel ----
    float ssz = 0.f, sst = 0.f;
    const int cBase = half * 16;
#pragma unroll
    for (int cc = 0; cc < 16; cc++) {
        const int c = cBase + cc;
        const float* pp = zt + c * CH_STRIDE + ty * ROWW + tx;  // top-left of 3x3
        const float* k9 = dws + c * 9;
        float acc;
        acc = pp[0] * k9[0];
        acc = fmaf(pp[1],          k9[1], acc);
        acc = fmaf(pp[2],          k9[2], acc);
        acc = fmaf(pp[ROWW],       k9[3], acc);
        float ctr = pp[ROWW + 1];
        acc = fmaf(ctr,            k9[4], acc);
        acc = fmaf(pp[ROWW + 2],   k9[5], acc);
        acc = fmaf(pp[2 * ROWW],     k9[6], acc);
        acc = fmaf(pp[2 * ROWW + 1], k9[7], acc);
        acc = fmaf(pp[2 * ROWW + 2], k9[8], acc);
        acc *= sc_s[c];
        zc_s[c * 128 + p] = acc;
        ssz = fmaf(ctr, ctr, ssz);
        sst = fmaf(acc, acc, sst);
    }
    ssz_s[half][p] = ssz;
    sst_s[half][p] = sst;
    __syncthreads();

    const float fz = ssz_s[0][p] + ssz_s[1][p];
    const float ft = sst_s[0][p] + sst_s[1][p];
    const float invz = 1.f / fmaxf(sqrtf(fz), 1e-6f);
    const float invt = 1.f / fmaxf(sqrtf(ft), 1e-6f);
    const float sIJ  = invz * invt;

    const int s = ((ty0 + ty) << 6) + (tx0 + tx);
    float* op = out + (size_t)b * COUT * HW + s;
    const float* ztC = zt + ty * ROWW + tx + ROWW + 1;   // center, channel-strided
    const float* zcp = zc_s + p;

    if (half == 0) {
        // z_norm (32 ch) + pairs k in [0, 248)
#pragma unroll
        for (int c = 0; c < CR; c++)
            op[(size_t)c * HW] = ztC[c * CH_STRIDE] * invz;
        emit_pairs<0, 248>(ztC, zcp, sIJ, op);
    } else {
        // pairs k in [248, 528)
        emit_pairs<248, 528>(ztC, zcp, sIJ, op);
    }
}

extern "C" void kernel_launch(void* const* d_in, const int* in_sizes, int n_in,
                              void* d_out, int out_size)
{
    const float* x     = (const float*)d_in[0];
    const float* w     = (const float*)d_in[1];
    const float* gamma = (const float*)d_in[2];
    const float* beta  = (const float*)d_in[3];
    const float* mean  = (const float*)d_in[4];
    const float* var   = (const float*)d_in[5];
    const float* dw    = (const float*)d_in[6];
    const float* scale = (const float*)d_in[7];

    k_reduce<<<dim3(256, 2), 256>>>(x, w, gamma, var);
    k_head<<<dim3(64 / TW, 64 / TH, B_), 256>>>(gamma, beta, mean, var,
                                                dw, scale, (float*)d_out);
}

// round 3
// speedup vs baseline: 1.3317x; 1.1412x over previous
#include <cuda_runtime.h>
#include <cstdint>

#define B_   16
#define CIN  256
#define CR   32
#define HW   4096          // 64*64
#define COUT 560           // 32 + 528

// 16 MB scratch: two K-half partial sums of the 1x1 conv (BN-scale folded,
// bias/ReLU deferred to k_head)
__device__ float g_zp[2][B_ * CR * HW];

__device__ __forceinline__ unsigned long long pack2(float lo, float hi) {
    unsigned long long r;
    asm("mov.b64 %0, {%1, %2};" : "=l"(r) : "r"(__float_as_uint(lo)), "r"(__float_as_uint(hi)));
    return r;
}
__device__ __forceinline__ unsigned long long fma2(unsigned long long a,
                                                   unsigned long long b,
                                                   unsigned long long c) {
    unsigned long long d;
    asm("fma.rn.f32x2 %0, %1, %2, %3;" : "=l"(d) : "l"(a), "l"(b), "l"(c));
    return d;
}
__device__ __forceinline__ void unpack2(unsigned long long v, float& lo, float& hi) {
    unsigned int l, h;
    asm("mov.b64 {%0, %1}, %2;" : "=r"(l), "=r"(h) : "l"(v));
    lo = __uint_as_float(l);
    hi = __uint_as_float(h);
}

// ---------------------------------------------------------------------------
// Kernel 1: 1x1 reduce conv, K-split 2.
// 128 threads = 2 channel-halves x 64 pixel-slots; each thread: 16 output
// channels (8 f32x2) x 4 pixels.  Per input channel: 4 LDS.128 -> 32 FFMA2
// (4x better smem-crossbar amortization than 1-pixel version).
// ---------------------------------------------------------------------------
__global__ __launch_bounds__(128, 4) void k_reduce(
    const float* __restrict__ x, const float* __restrict__ w,
    const float* __restrict__ gamma, const float* __restrict__ var)
{
    __shared__ __align__(16) float wsm[128 * CR];  // [c_local][o], BN inv folded
    __shared__ float inv_s[CR];

    const int tid = threadIdx.x;
    const int kh  = blockIdx.y;            // input channels kh*128 .. +128

    if (tid < CR)
        inv_s[tid] = gamma[tid] * rsqrtf(var[tid] + 1e-5f);
    __syncthreads();
    for (int i = tid; i < 128 * CR; i += 128) {
        int c = i >> 5, o = i & 31;        // c local
        wsm[i] = w[o * CIN + kh * 128 + c] * inv_s[o];
    }
    __syncthreads();

    const int h  = tid >> 6;               // channel half (uniform per warp-pair)
    const int s  = tid & 63;               // pixel slot
    const int base = blockIdx.x * 256;     // 256 pixels per block
    const int b    = base >> 12;           // 16 blocks per image
    const int s0   = (base & 4095) + s;

    const float* xp = x + ((size_t)(b * CIN + kh * 128) << 12) + s0;

    unsigned long long acc[4][8];
#pragma unroll
    for (int k = 0; k < 4; k++)
#pragma unroll
        for (int m = 0; m < 8; m++) acc[k][m] = 0ull;

#pragma unroll 2
    for (int c = 0; c < 128; c++) {
        const float* xc = xp + (c << 12);
        unsigned long long a2[4];
#pragma unroll
        for (int k = 0; k < 4; k++) {
            float a = __ldg(xc + k * 64);
            a2[k] = pack2(a, a);
        }
        const ulonglong2* wr =
            reinterpret_cast<const ulonglong2*>(wsm + c * CR + h * 16);
#pragma unroll
        for (int q = 0; q < 4; q++) {
            ulonglong2 w2 = wr[q];          // 4 output channels (2 f32x2)
#pragma unroll
            for (int k = 0; k < 4; k++) {
                acc[k][2 * q]     = fma2(a2[k], w2.x, acc[k][2 * q]);
                acc[k][2 * q + 1] = fma2(a2[k], w2.y, acc[k][2 * q + 1]);
            }
        }
    }

    float* zp = g_zp[kh] + ((size_t)(b * CR) << 12) + s0;
#pragma unroll
    for (int k = 0; k < 4; k++) {
#pragma unroll
        for (int m = 0; m < 8; m++) {
            float v0, v1;
            unpack2(acc[k][m], v0, v1);
            const int ch = h * 16 + 2 * m;
            zp[((size_t)ch << 12) + k * 64]       = v0;
            zp[((size_t)(ch + 1) << 12) + k * 64] = v1;
        }
    }
}

// ---------------------------------------------------------------------------
// Kernel 2: combine K-halves + bias + ReLU, depthwise 3x3 + scale, dual
// L2-normalize, triu pair products, concat write.
// 32x4 pixel tile, 256 threads = 2 threads/pixel (channel split for conv,
// pair-range split for emit).
// ---------------------------------------------------------------------------
#define TW 32
#define TH 4
#define ROWW 34                       // TW + 2 halo
#define CH_STRIDE (6 * ROWW)          // 204 floats per channel tile

// flattened triu emit: k runs [KLO,KHI), carried (i,j) starting at (I0,J0)
template<int KLO, int KHI, int I0, int J0>
__device__ __forceinline__ void emit_pairs(const float* __restrict__ ztC,
                                           const float* __restrict__ zcp,
                                           float sIJ, float* __restrict__ op)
{
    int i = I0, j = J0;
    float zi = ztC[i * CH_STRIDE] * sIJ;
    float* p = op + (size_t)(CR + KLO) * HW;
#pragma unroll 8
    for (int k = KLO; k < KHI; k++) {
        float zj = zcp[j * 128];
        *p = zi * zj;
        p += HW;
        if (++j == CR) {
            ++i;
            j = i;
            if (i < CR) zi = ztC[i * CH_STRIDE] * sIJ;
        }
    }
}

__global__ __launch_bounds__(256, 4) void k_head(
    const float* __restrict__ gamma, const float* __restrict__ beta,
    const float* __restrict__ mean,  const float* __restrict__ var,
    const float* __restrict__ dw,    const float* __restrict__ scale,
    float* __restrict__ out)
{
    __shared__ float zt[CR * CH_STRIDE];     // relu'd z tile with halo (25.5KB)
    __shared__ float zc_s[CR * 128];         // conv*scale per pixel (16KB)
    __shared__ float ssz_s[2][128];
    __shared__ float sst_s[2][128];
    __shared__ float dws[CR * 9];
    __shared__ float sc_s[CR];
    __shared__ float bias_s[CR];

    const int tid  = threadIdx.x;
    const int b    = blockIdx.z;
    const int ty0  = blockIdx.y * TH;
    const int tx0  = blockIdx.x * TW;
    const int half = tid >> 7;               // 0 or 1
    const int p    = tid & 127;              // pixel within tile
    const int ty   = p >> 5;
    const int tx   = p & 31;

    if (tid < CR) {
        float inv = gamma[tid] * rsqrtf(var[tid] + 1e-5f);
        bias_s[tid] = beta[tid] - mean[tid] * inv;
        sc_s[tid]   = scale[tid];
    }
    for (int i = tid; i < CR * 9; i += 256) dws[i] = dw[i];
    __syncthreads();

    // ---- load halo'd tile: z = relu(part0 + part1 + bias) ----
    const float* z0 = g_zp[0] + ((size_t)(b * CR) << 12);
    const float* z1 = g_zp[1] + ((size_t)(b * CR) << 12);
    for (int i = tid; i < CR * CH_STRIDE; i += 256) {
        int c  = i / CH_STRIDE;
        int r  = i - c * CH_STRIDE;
        int y  = r / ROWW;
        int xx = r - y * ROWW;
        int gy = ty0 - 1 + y;
        int gx = tx0 - 1 + xx;
        float v = 0.f;
        if ((unsigned)gy < 64u && (unsigned)gx < 64u) {
            int off = (c << 12) + (gy << 6) + gx;
            v = fmaxf(z0[off] + z1[off] + bias_s[c], 0.f);
        }
        zt[i] = v;
    }
    __syncthreads();

    // ---- conv: each thread does 16 channels for its pixel ----
    float ssz = 0.f, sst = 0.f;
    const int cBase = half * 16;
#pragma unroll
    for (int cc = 0; cc < 16; cc++) {
        const int c = cBase + cc;
        const float* pp = zt + c * CH_STRIDE + ty * ROWW + tx;  // top-left of 3x3
        const float* k9 = dws + c * 9;
        float acc;
        acc = pp[0] * k9[0];
        acc = fmaf(pp[1],            k9[1], acc);
        acc = fmaf(pp[2],            k9[2], acc);
        acc = fmaf(pp[ROWW],         k9[3], acc);
        float ctr = pp[ROWW + 1];
        acc = fmaf(ctr,              k9[4], acc);
        acc = fmaf(pp[ROWW + 2],     k9[5], acc);
        acc = fmaf(pp[2 * ROWW],     k9[6], acc);
        acc = fmaf(pp[2 * ROWW + 1], k9[7], acc);
        acc = fmaf(pp[2 * ROWW + 2], k9[8], acc);
        acc *= sc_s[c];
        zc_s[c * 128 + p] = acc;
        ssz = fmaf(ctr, ctr, ssz);
        sst = fmaf(acc, acc, sst);
    }
    ssz_s[half][p] = ssz;
    sst_s[half][p] = sst;
    __syncthreads();

    const float fz = ssz_s[0][p] + ssz_s[1][p];
    const float ft = sst_s[0][p] + sst_s[1][p];
    const float invz = 1.f / fmaxf(sqrtf(fz), 1e-6f);
    const float invt = 1.f / fmaxf(sqrtf(ft), 1e-6f);
    const float sIJ  = invz * invt;

    const int s = ((ty0 + ty) << 6) + (tx0 + tx);
    float* op = out + (size_t)b * COUT * HW + s;
    const float* ztC = zt + ty * ROWW + tx + ROWW + 1;   // center, channel-strided
    const float* zcp = zc_s + p;

    if (half == 0) {
        // z_norm (32 ch) + pairs k in [0, 248):  (i,j) starts (0,0)
#pragma unroll
        for (int c = 0; c < CR; c++)
            op[(size_t)c * HW] = ztC[c * CH_STRIDE] * invz;
        emit_pairs<0, 248, 0, 0>(ztC, zcp, sIJ, op);
    } else {
        // pairs k in [248, 528):  k=248 -> (i,j)=(8,28)
        emit_pairs<248, 528, 8, 28>(ztC, zcp, sIJ, op);
    }
}

extern "C" void kernel_launch(void* const* d_in, const int* in_sizes, int n_in,
                              void* d_out, int out_size)
{
    const float* x     = (const float*)d_in[0];
    const float* w     = (const float*)d_in[1];
    const float* gamma = (const float*)d_in[2];
    const float* beta  = (const float*)d_in[3];
    const float* mean  = (const float*)d_in[4];
    const float* var   = (const float*)d_in[5];
    const float* dw    = (const float*)d_in[6];
    const float* scale = (const float*)d_in[7];

    k_reduce<<<dim3(256, 2), 128>>>(x, w, gamma, var);
    k_head<<<dim3(64 / TW, 64 / TH, B_), 256>>>(gamma, beta, mean, var,
                                                dw, scale, (float*)d_out);
}

// round 4
// speedup vs baseline: 1.6040x; 1.2044x over previous
#include <cuda_runtime.h>
#include <cstdint>

#define B_   16
#define CIN  256
#define CR   32
#define HW   4096          // 64*64
#define COUT 560           // 32 + 528

// 16 MB scratch: two K-half partial sums of the 1x1 conv (BN-scale folded,
// bias/ReLU deferred to k_head)
__device__ float g_zp[2][B_ * CR * HW];

__device__ __forceinline__ unsigned long long pack2(float lo, float hi) {
    unsigned long long r;
    asm("mov.b64 %0, {%1, %2};" : "=l"(r) : "r"(__float_as_uint(lo)), "r"(__float_as_uint(hi)));
    return r;
}
__device__ __forceinline__ unsigned long long fma2(unsigned long long a,
                                                   unsigned long long b,
                                                   unsigned long long c) {
    unsigned long long d;
    asm("fma.rn.f32x2 %0, %1, %2, %3;" : "=l"(d) : "l"(a), "l"(b), "l"(c));
    return d;
}
__device__ __forceinline__ void unpack2(unsigned long long v, float& lo, float& hi) {
    unsigned int l, h;
    asm("mov.b64 {%0, %1}, %2;" : "=r"(l), "=r"(h) : "l"(v));
    lo = __uint_as_float(l);
    hi = __uint_as_float(h);
}

// ---------------------------------------------------------------------------
// Kernel 1: 1x1 reduce conv, K-split 2.
// 256 threads = 2 channel-halves x 128 pixel-pair slots; each thread:
// 16 output channels x 2 adjacent pixels (LDG.64), 16 f32x2 accumulators.
// Small acc state -> ~8 warps/SMSP for DRAM-latency hiding.
// ---------------------------------------------------------------------------
__global__ __launch_bounds__(256, 4) void k_reduce(
    const float* __restrict__ x, const float* __restrict__ w,
    const float* __restrict__ gamma, const float* __restrict__ var)
{
    __shared__ __align__(16) float wsm[128 * CR];  // [c_local][o], BN inv folded
    __shared__ float inv_s[CR];

    const int tid = threadIdx.x;
    const int kh  = blockIdx.y;            // input channels kh*128 .. +128

    if (tid < CR)
        inv_s[tid] = gamma[tid] * rsqrtf(var[tid] + 1e-5f);
    __syncthreads();
    for (int i = tid; i < 128 * CR; i += 256) {
        int c = i >> 5, o = i & 31;        // c local
        wsm[i] = w[o * CIN + kh * 128 + c] * inv_s[o];
    }
    __syncthreads();

    const int h    = tid >> 7;             // channel half (warp-uniform)
    const int slot = tid & 127;            // pixel-pair slot
    const int base = blockIdx.x * 256;     // 256 pixels per block
    const int b    = base >> 12;           // 16 blocks per image
    const int s0   = (base & 4095) + slot * 2;

    const float* xp = x + ((size_t)(b * CIN + kh * 128) << 12) + s0;

    unsigned long long acc0[8], acc1[8];   // [q] for px0 / px1
#pragma unroll
    for (int m = 0; m < 8; m++) { acc0[m] = 0ull; acc1[m] = 0ull; }

#pragma unroll 4
    for (int c = 0; c < 128; c++) {
        float2 a = *reinterpret_cast<const float2*>(xp + (c << 12));  // LDG.64
        unsigned long long a0 = pack2(a.x, a.x);
        unsigned long long a1 = pack2(a.y, a.y);
        const ulonglong2* wr =
            reinterpret_cast<const ulonglong2*>(wsm + c * CR + h * 16);
#pragma unroll
        for (int q = 0; q < 4; q++) {
            ulonglong2 w2 = wr[q];          // 4 output channels (2 f32x2)
            acc0[2 * q]     = fma2(a0, w2.x, acc0[2 * q]);
            acc0[2 * q + 1] = fma2(a0, w2.y, acc0[2 * q + 1]);
            acc1[2 * q]     = fma2(a1, w2.x, acc1[2 * q]);
            acc1[2 * q + 1] = fma2(a1, w2.y, acc1[2 * q + 1]);
        }
    }

    float* zp = g_zp[kh] + ((size_t)(b * CR) << 12) + s0;
#pragma unroll
    for (int m = 0; m < 8; m++) {
        float p0lo, p0hi, p1lo, p1hi;
        unpack2(acc0[m], p0lo, p0hi);
        unpack2(acc1[m], p1lo, p1hi);
        const int ch = h * 16 + 2 * m;
        *reinterpret_cast<float2*>(zp + ((size_t)ch << 12))       = make_float2(p0lo, p1lo);
        *reinterpret_cast<float2*>(zp + ((size_t)(ch + 1) << 12)) = make_float2(p0hi, p1hi);
    }
}

// ---------------------------------------------------------------------------
// Kernel 2: combine K-halves + bias + ReLU, depthwise 3x3 + scale, dual
// L2-normalize, triu pair products, concat write.
// 32x4 pixel tile, 256 threads.
//  conv phase: 2 thr/pixel (16 ch each)
//  emit phase: 8 warps x 32 pixel-groups; each thread emits 70 output
//  channels for 4 adjacent pixels via STG.128 (warp-uniform k-range).
// ---------------------------------------------------------------------------
#define TW 32
#define TH 4
#define ROWW 34                       // TW + 2 halo
#define CH_STRIDE (6 * ROWW)          // 204 floats per channel tile

__global__ __launch_bounds__(256, 4) void k_head(
    const float* __restrict__ gamma, const float* __restrict__ beta,
    const float* __restrict__ mean,  const float* __restrict__ var,
    const float* __restrict__ dw,    const float* __restrict__ scale,
    float* __restrict__ out)
{
    __shared__ float zt[CR * CH_STRIDE];     // relu'd z tile with halo (25.5KB)
    __shared__ __align__(16) float zc_s[CR * 128];  // conv*scale per pixel (16KB)
    __shared__ float ssz_s[2][128];
    __shared__ float sst_s[2][128];
    __shared__ __align__(16) float invz_s[128];
    __shared__ __align__(16) float invt_s[128];
    __shared__ float dws[CR * 9];
    __shared__ float sc_s[CR];
    __shared__ float bias_s[CR];

    const int tid  = threadIdx.x;
    const int b    = blockIdx.z;
    const int ty0  = blockIdx.y * TH;
    const int tx0  = blockIdx.x * TW;
    const int half = tid >> 7;               // 0 or 1
    const int p    = tid & 127;              // pixel within tile
    const int pty  = p >> 5;
    const int ptx  = p & 31;

    if (tid < CR) {
        float inv = gamma[tid] * rsqrtf(var[tid] + 1e-5f);
        bias_s[tid] = beta[tid] - mean[tid] * inv;
        sc_s[tid]   = scale[tid];
    }
    for (int i = tid; i < CR * 9; i += 256) dws[i] = dw[i];
    __syncthreads();

    // ---- load halo'd tile: z = relu(part0 + part1 + bias) ----
    const float* z0 = g_zp[0] + ((size_t)(b * CR) << 12);
    const float* z1 = g_zp[1] + ((size_t)(b * CR) << 12);
    for (int i = tid; i < CR * CH_STRIDE; i += 256) {
        int c  = i / CH_STRIDE;
        int r  = i - c * CH_STRIDE;
        int y  = r / ROWW;
        int xx = r - y * ROWW;
        int gy = ty0 - 1 + y;
        int gx = tx0 - 1 + xx;
        float v = 0.f;
        if ((unsigned)gy < 64u && (unsigned)gx < 64u) {
            int off = (c << 12) + (gy << 6) + gx;
            v = fmaxf(z0[off] + z1[off] + bias_s[c], 0.f);
        }
        zt[i] = v;
    }
    __syncthreads();

    // ---- conv: each thread does 16 channels for its pixel ----
    {
        float ssz = 0.f, sst = 0.f;
        const int cBase = half * 16;
#pragma unroll
        for (int cc = 0; cc < 16; cc++) {
            const int c = cBase + cc;
            const float* pp = zt + c * CH_STRIDE + pty * ROWW + ptx;
            const float* k9 = dws + c * 9;
            float acc;
            acc = pp[0] * k9[0];
            acc = fmaf(pp[1],            k9[1], acc);
            acc = fmaf(pp[2],            k9[2], acc);
            acc = fmaf(pp[ROWW],         k9[3], acc);
            float ctr = pp[ROWW + 1];
            acc = fmaf(ctr,              k9[4], acc);
            acc = fmaf(pp[ROWW + 2],     k9[5], acc);
            acc = fmaf(pp[2 * ROWW],     k9[6], acc);
            acc = fmaf(pp[2 * ROWW + 1], k9[7], acc);
            acc = fmaf(pp[2 * ROWW + 2], k9[8], acc);
            acc *= sc_s[c];
            zc_s[c * 128 + p] = acc;
            ssz = fmaf(ctr, ctr, ssz);
            sst = fmaf(acc, acc, sst);
        }
        ssz_s[half][p] = ssz;
        sst_s[half][p] = sst;
    }
    __syncthreads();

    // per-pixel norms (written redundantly by both halves — same value)
    {
        const float fz = ssz_s[0][p] + ssz_s[1][p];
        const float ft = sst_s[0][p] + sst_s[1][p];
        invz_s[p] = 1.f / fmaxf(sqrtf(fz), 1e-6f);
        invt_s[p] = 1.f / fmaxf(sqrtf(ft), 1e-6f);
    }
    __syncthreads();

    // ---- emit: warp e handles output channels [70e, 70e+70) for its
    //      lane's 4-adjacent-pixel group ----
    const int e  = tid >> 5;                 // warp id, warp-uniform k-range
    const int g  = tid & 31;                 // pixel group
    const int gy = g >> 3;                   // row within tile
    const int gx = (g & 7) * 4;              // 4-px column start
    const int p0 = gy * 32 + gx;

    const float4 iz4 = *reinterpret_cast<const float4*>(&invz_s[p0]);
    const float4 it4 = *reinterpret_cast<const float4*>(&invt_s[p0]);

    const int s = ((ty0 + gy) << 6) + tx0 + gx;
    float* op = out + (size_t)b * COUT * HW + s;
    const float* ctr = zt + gy * ROWW + gx + ROWW + 1;   // + c*CH_STRIDE

    int ch = 70 * e;
    const int chHi = ch + 70;

    // z_norm channels (only warp 0 has ch < 32)
    for (; ch < 32 && ch < chHi; ch++) {
        const float* zz = ctr + ch * CH_STRIDE;
        float4 o;
        o.x = zz[0] * iz4.x;
        o.y = zz[1] * iz4.y;
        o.z = zz[2] * iz4.z;
        o.w = zz[3] * iz4.w;
        *reinterpret_cast<float4*>(op + (size_t)ch * HW) = o;
    }

    if (ch < chHi) {
        int k = ch - 32;
        // find i: largest i with base(i) <= k, base(i) = 32i - i(i-1)/2
        int i = 0;
        while (32 * (i + 1) - ((i + 1) * i) / 2 <= k) i++;
        int j = i + (k - (32 * i - (i * (i - 1)) / 2));

        float4 s4;
        s4.x = iz4.x * it4.x;
        s4.y = iz4.y * it4.y;
        s4.z = iz4.z * it4.z;
        s4.w = iz4.w * it4.w;

        const float* zz = ctr + i * CH_STRIDE;
        float4 zin;
        zin.x = zz[0] * s4.x;
        zin.y = zz[1] * s4.y;
        zin.z = zz[2] * s4.z;
        zin.w = zz[3] * s4.w;

        float* pdst = op + (size_t)ch * HW;
#pragma unroll 4
        for (; ch < chHi; ch++) {
            float4 zj = *reinterpret_cast<const float4*>(&zc_s[j * 128 + p0]);
            float4 o;
            o.x = zin.x * zj.x;
            o.y = zin.y * zj.y;
            o.z = zin.z * zj.z;
            o.w = zin.w * zj.w;
            *reinterpret_cast<float4*>(pdst) = o;
            pdst += HW;
            if (++j == CR) {
                ++i;
                j = i;
                if (i < CR) {
                    const float* z2 = ctr + i * CH_STRIDE;
                    zin.x = z2[0] * s4.x;
                    zin.y = z2[1] * s4.y;
                    zin.z = z2[2] * s4.z;
                    zin.w = z2[3] * s4.w;
                }
            }
        }
    }
}

extern "C" void kernel_launch(void* const* d_in, const int* in_sizes, int n_in,
                              void* d_out, int out_size)
{
    const float* x     = (const float*)d_in[0];
    const float* w     = (const float*)d_in[1];
    const float* gamma = (const float*)d_in[2];
    const float* beta  = (const float*)d_in[3];
    const float* mean  = (const float*)d_in[4];
    const float* var   = (const float*)d_in[5];
    const float* dw    = (const float*)d_in[6];
    const float* scale = (const float*)d_in[7];

    k_reduce<<<dim3(256, 2), 256>>>(x, w, gamma, var);
    k_head<<<dim3(64 / TW, 64 / TH, B_), 256>>>(gamma, beta, mean, var,
                                                dw, scale, (float*)d_out);
}